// round 11
// baseline (speedup 1.0000x reference)
#include <cuda_runtime.h>
#include <cstdint>

#define T_DIM 256
#define B_DIM 128
#define DIN 20
#define H_DIM 1024
#define OUT_DIM 1095
#define L_DIM 3
#define M_ALL (T_DIM * B_DIM)   // 32768
#define N_SRU (3 * H_DIM)       // 3072
#define N3PAD 1152
#define K8CNT (H_DIM / 8)       // 128
#define KPCNT (K8CNT / 2)       // 64 k8-pairs
#define N8_SRU (N_SRU / 8)      // 384
#define N8_W3 (N3PAD / 8)       // 144

// ---------------- scratch ----------------
__device__ float g_h[(size_t)M_ALL * H_DIM];                      // 134 MB
__device__ float g_U[(size_t)M_ALL * N_SRU];                      // 402 MB
__device__ uint4 g_Af[(size_t)(M_ALL / 16) * K8CNT * 32];         // 134 MB
__device__ float g_WT[(size_t)L_DIM * N_SRU * H_DIM];             // B frags (SRU)
__device__ float g_W3T[(size_t)N3PAD * H_DIM];                    // B frags (W3)

__device__ __forceinline__ uint32_t f2tf32(float v) {
    uint32_t u;
    asm("cvt.rna.tf32.f32 %0, %1;" : "=r"(u) : "f"(v));
    return u;
}
__device__ __forceinline__ float f2tf32f(float v) { return __uint_as_float(f2tf32(v)); }

// ---------------------------------------------------------------------------
// Prep B (all layers, ONE launch): W[K][N] -> fragment-pair order, kp-major:
// BF[((kp*N8)+n8)*32+lane] = uint4{ b0(k8=2kp), b1(2kp), b0(2kp+1), b1(2kp+1) }
// b0 = tf32(W[k8*8+(lane&3)][n8*8+(lane>>2)]), b1 = same k+4. n >= N -> 0.
// blockIdx.y: 0..2 = SRU layers, 3 = W3 (padded to N3PAD).
// ---------------------------------------------------------------------------
__global__ void wfrag_all_kernel(const float* __restrict__ Wsru,
                                 const float* __restrict__ W3,
                                 uint4* __restrict__ BF,
                                 uint4* __restrict__ BF3,
                                 size_t layerStride) {
    const int layer = blockIdx.y;
    const float* W;
    uint4* dst;
    int N, N8;
    if (layer < 3) {
        W = Wsru + (size_t)layer * H_DIM * N_SRU;
        dst = BF + (size_t)layer * layerStride;
        N = N_SRU; N8 = N8_SRU;
    } else {
        W = W3; dst = BF3; N = OUT_DIM; N8 = N8_W3;
    }
    int task = blockIdx.x * 8 + (threadIdx.x >> 5);
    if (task >= N8 * KPCNT) return;
    int kp = task / N8;
    int n8 = task - kp * N8;
    int lane = threadIdx.x & 31;
    int n = n8 * 8 + (lane >> 2);
    int kq = kp * 16 + (lane & 3);
    float b0 = 0.0f, b1 = 0.0f, b2 = 0.0f, b3 = 0.0f;
    if (n < N) {
        b0 = W[(size_t)kq * N + n];
        b1 = W[(size_t)(kq + 4) * N + n];
        b2 = W[(size_t)(kq + 8) * N + n];
        b3 = W[(size_t)(kq + 12) * N + n];
    }
    dst[((size_t)kp * N8 + n8) * 32 + lane] =
        make_uint4(f2tf32(b0), f2tf32(b1), f2tf32(b2), f2tf32(b3));
}

// ---------------------------------------------------------------------------
// Prep A: h[M][K] -> per-lane A fragments (layout [m16][k8][lane] uint4)
// ---------------------------------------------------------------------------
__global__ void afrag_kernel(const float* __restrict__ h, uint4* __restrict__ Af) {
    __shared__ float s[64][33];
    const int r0 = blockIdx.x * 64;
    const int c0 = blockIdx.y * 32;
    const int tid = threadIdx.x;
    const int lr = tid >> 3, lc = (tid & 7) * 4;
    {
        float4 v = *(const float4*)(h + (size_t)(r0 + lr) * H_DIM + c0 + lc);
        s[lr][lc] = v.x; s[lr][lc + 1] = v.y; s[lr][lc + 2] = v.z; s[lr][lc + 3] = v.w;
        float4 w = *(const float4*)(h + (size_t)(r0 + lr + 32) * H_DIM + c0 + lc);
        s[lr + 32][lc] = w.x; s[lr + 32][lc + 1] = w.y;
        s[lr + 32][lc + 2] = w.z; s[lr + 32][lc + 3] = w.w;
    }
    __syncthreads();
    const int warp = tid >> 5, lane = tid & 31;
    const int gr = lane >> 2, gc = lane & 3;
#pragma unroll
    for (int i = 0; i < 2; i++) {
        int sblk = warp * 2 + i;
        int mi = sblk >> 2, ki = sblk & 3;
        uint4 v;
        v.x = __float_as_uint(s[mi * 16 + gr][ki * 8 + gc]);
        v.y = __float_as_uint(s[mi * 16 + gr + 8][ki * 8 + gc]);
        v.z = __float_as_uint(s[mi * 16 + gr][ki * 8 + gc + 4]);
        v.w = __float_as_uint(s[mi * 16 + gr + 8][ki * 8 + gc + 4]);
        Af[((size_t)(r0 / 16 + mi) * K8CNT + (c0 / 8 + ki)) * 32 + lane] = v;
    }
}

// ---------------------------------------------------------------------------
// Dense1
// ---------------------------------------------------------------------------
__global__ void dense1_kernel(const float* __restrict__ x,
                              const float* __restrict__ W1,
                              const float* __restrict__ b1,
                              float* __restrict__ h) {
    int row = blockIdx.x;
    __shared__ float xs[DIN];
    if (threadIdx.x < DIN) xs[threadIdx.x] = x[(size_t)row * DIN + threadIdx.x];
    __syncthreads();
    for (int j = threadIdx.x; j < H_DIM; j += blockDim.x) {
        float acc = b1[j];
#pragma unroll
        for (int k = 0; k < DIN; k++) acc += xs[k] * W1[k * H_DIM + j];
        h[(size_t)row * H_DIM + j] = f2tf32f(acc);
    }
}

// ---------------------------------------------------------------------------
// TF32 GEMM, fragment-direct: no smem, no barriers.
// B loads: contiguous 4KB block per warp per kp (ni offsets = 512B immediates).
// A loads: constant offsets {0,512B,64KB,64KB+512B} off an advancing pointer.
// ---------------------------------------------------------------------------
template <bool GUARD_N>
__global__ __launch_bounds__(256, 2) void tf32_gemm(
    const uint4* __restrict__ Af, const uint4* __restrict__ Bf,
    float* __restrict__ C, int ldC, int Nvalid, int N8,
    const float* __restrict__ bias) {
    const int tid = threadIdx.x;
    const int lane = tid & 31;
    const int warp = tid >> 5;
    const int wm = warp >> 1;
    const int wn = warp & 1;

    const uint4* Ap = Af + ((size_t)(blockIdx.y * 8 + wm * 2) * K8CNT) * 32 + lane;
    const uint4* Bp = Bf + (size_t)(blockIdx.x * 16 + wn * 8) * 32 + lane;
    const size_t bStep = (size_t)N8 * 32;

    float acc[2][8][4];
#pragma unroll
    for (int mi = 0; mi < 2; mi++)
#pragma unroll
        for (int ni = 0; ni < 8; ni++)
#pragma unroll
            for (int j = 0; j < 4; j++) acc[mi][ni][j] = 0.0f;

    for (int kp = 0; kp < KPCNT; kp++) {
        uint4 b4[8];
#pragma unroll
        for (int ni = 0; ni < 8; ni++)
            b4[ni] = Bp[ni * 32];                  // 512B immediates
        Bp += bStep;
        uint4 a4[2][2];
#pragma unroll
        for (int s = 0; s < 2; s++)
#pragma unroll
            for (int mi = 0; mi < 2; mi++)
                a4[s][mi] = Ap[(size_t)mi * (K8CNT * 32) + s * 32];
        Ap += 64;

#pragma unroll
        for (int s = 0; s < 2; s++)
#pragma unroll
            for (int mi = 0; mi < 2; mi++)
#pragma unroll
                for (int ni = 0; ni < 8; ni++) {
                    uint32_t bx = s ? b4[ni].z : b4[ni].x;
                    uint32_t by = s ? b4[ni].w : b4[ni].y;
                    asm volatile(
                        "mma.sync.aligned.m16n8k8.row.col.f32.tf32.tf32.f32 "
                        "{%0,%1,%2,%3}, {%4,%5,%6,%7}, {%8,%9}, {%0,%1,%2,%3};\n"
                        : "+f"(acc[mi][ni][0]), "+f"(acc[mi][ni][1]),
                          "+f"(acc[mi][ni][2]), "+f"(acc[mi][ni][3])
                        : "r"(a4[s][mi].x), "r"(a4[s][mi].y),
                          "r"(a4[s][mi].z), "r"(a4[s][mi].w),
                          "r"(bx), "r"(by));
                }
    }

    // epilogue
    const int gr = lane >> 2;
    const int gc = (lane & 3) * 2;
#pragma unroll
    for (int mi = 0; mi < 2; mi++) {
        int r0 = blockIdx.y * 128 + wm * 32 + mi * 16 + gr;
#pragma unroll
        for (int ni = 0; ni < 8; ni++) {
            int c0 = blockIdx.x * 128 + wn * 64 + ni * 8 + gc;
            float b0 = 0.0f, b1 = 0.0f;
            if (bias) {
                if (!GUARD_N || c0 < Nvalid) b0 = bias[c0];
                if (!GUARD_N || c0 + 1 < Nvalid) b1 = bias[c0 + 1];
            }
            float* Cp0 = C + (size_t)r0 * ldC + c0;
            float* Cp1 = C + (size_t)(r0 + 8) * ldC + c0;
            if (!GUARD_N || c0 < Nvalid) {
                Cp0[0] = acc[mi][ni][0] + b0;
                Cp1[0] = acc[mi][ni][2] + b0;
            }
            if (!GUARD_N || c0 + 1 < Nvalid) {
                Cp0[1] = acc[mi][ni][1] + b1;
                Cp1[1] = acc[mi][ni][3] + b1;
            }
        }
    }
}

// ---------------------------------------------------------------------------
// SRU scan
// ---------------------------------------------------------------------------
__global__ void sru_scan_kernel(const float* __restrict__ U,
                                float* __restrict__ h,
                                const float* __restrict__ bf,
                                const float* __restrict__ br,
                                float* __restrict__ c_out) {
    int idx = blockIdx.x * blockDim.x + threadIdx.x;
    int b = idx / H_DIM;
    int hh = idx - b * H_DIM;
    float bfv = bf[hh];
    float brv = br[hh];
    float c = 0.0f;

    const float* Ub = U + (size_t)b * N_SRU + hh;
    float* hb = h + (size_t)b * H_DIM + hh;

    for (int t = 0; t < T_DIM; t++) {
        const float* Ut = Ub + (size_t)t * B_DIM * N_SRU;
        float z = Ut[0];
        float fp = Ut[H_DIM];
        float rp = Ut[2 * H_DIM];
        float f = 1.0f / (1.0f + __expf(-(fp + bfv)));
        float r = 1.0f / (1.0f + __expf(-(rp + brv)));
        c = f * c + (1.0f - f) * z;
        float* hp = hb + (size_t)t * B_DIM * H_DIM;
        float hin = *hp;
        *hp = f2tf32f(r * c + (1.0f - r) * hin);
    }
    c_out[idx] = c;
}

// ---------------------------------------------------------------------------
// Launch — order puts tf32_gemm<false> at process launch slot #4
// (slots 1-3: wfrag_all, dense1, afrag) so the profiler samples the GEMM.
// ---------------------------------------------------------------------------
extern "C" void kernel_launch(void* const* d_in, const int* in_sizes, int n_in,
                              void* d_out, int out_size) {
    const float* x     = (const float*)d_in[0];
    const float* W1    = (const float*)d_in[2];
    const float* b1    = (const float*)d_in[3];
    const float* W_sru = (const float*)d_in[4];
    const float* bf    = (const float*)d_in[5];
    const float* br    = (const float*)d_in[6];
    const float* W3    = (const float*)d_in[7];
    const float* b3    = (const float*)d_in[8];
    float* out = (float*)d_out;

    float *h_buf, *U_buf, *WTf, *W3Tf;
    uint4* Af;
    cudaGetSymbolAddress((void**)&h_buf, g_h);
    cudaGetSymbolAddress((void**)&U_buf, g_U);
    cudaGetSymbolAddress((void**)&Af, g_Af);
    cudaGetSymbolAddress((void**)&WTf, g_WT);
    cudaGetSymbolAddress((void**)&W3Tf, g_W3T);
    uint4* BF = (uint4*)WTf;
    uint4* BF3 = (uint4*)W3Tf;
    const size_t bfLayerStride = (size_t)N8_SRU * KPCNT * 32;  // uint4 elems

    // 1: all B fragment preps in one launch
    {
        dim3 grd(N8_SRU * KPCNT / 8, 4);   // 3072 x 4 (layer 3 guards internally)
        wfrag_all_kernel<<<grd, 256>>>(W_sru, W3, BF, BF3, bfLayerStride);
    }

    // 2: dense1
    dense1_kernel<<<M_ALL, 256>>>(x, W1, b1, h_buf);

    // 3: A fragments
    dim3 agrid(M_ALL / 64, H_DIM / 32);
    afrag_kernel<<<agrid, 256>>>(h_buf, Af);

    float* c_base = out + (size_t)M_ALL * OUT_DIM;
    for (int l = 0; l < L_DIM; l++) {
        // 4 (l=0): the GEMM — profiler target
        dim3 grid(N_SRU / 128, M_ALL / 128);
        tf32_gemm<false><<<grid, 256>>>(
            Af, BF + l * bfLayerStride, U_buf, N_SRU, N_SRU, N8_SRU, nullptr);
        sru_scan_kernel<<<(B_DIM * H_DIM) / 256, 256>>>(
            U_buf, h_buf, bf + l * H_DIM, br + l * H_DIM,
            c_base + (size_t)l * B_DIM * H_DIM);
        afrag_kernel<<<agrid, 256>>>(h_buf, Af);
    }

    dim3 grid3(N3PAD / 128, M_ALL / 128);
    tf32_gemm<true><<<grid3, 256>>>(Af, BF3, out, OUT_DIM, OUT_DIM, N8_W3, b3);
}